// round 14
// baseline (speedup 1.0000x reference)
#include <cuda_runtime.h>
#include <cuda_fp16.h>
#include <math.h>
#include <cstdint>

#define NN 8
#define BB 64
#define TT 256
#define DIN 64
#define HH 512
#define MMd 512
#define OO 7

// ---------------- device globals (no allocation allowed) ----------------
__device__ __half g_z[BB * TT * HH];                 // input-layer output, fp16, [b][t][H]
__device__ __half g_h0[4][NN * BB * HH];             // 4-deep h0 ring (role skew slack)
__device__ __half g_h1[2][NN * BB * HH];
__device__ __half g_y[(size_t)NN * BB * TT * HH];    // layer-1 outputs, fp16
__device__ __half g_wih0[NN * 4 * HH * HH];          // fp16 weight copies
__device__ __half g_whh0[NN * 4 * HH * HH];
__device__ __half g_wih1[NN * 4 * HH * HH];
__device__ __half g_whh1[NN * 4 * HH * HH];
__device__ __half g_wh1h[NN * MMd * HH];             // head Wh1 fp16

// per-ensemble, per-role barrier state (16 CTAs per group)
__device__ unsigned g_cnt2[2][NN];
__device__ unsigned g_ep2[2][NN];

// persist smem layout (dynamic):
//   A stage s: @ s*32768, 32KB each = 2 subs x [128 rows][128B] swizzled
//   B stage s: @ 65536 + s*16384, 16KB each = 2 subs x [64 rows][128B]
//   c state float[2080] @ 98304 (jlocal*65 + b, padded stride vs bank conflicts)
//   bias float[128] @ 106624 ; total 107136.
#define SMA(s)    ((s) * 32768)
#define SMB(s)    (65536 + (s) * 16384)
#define SM_CSM    98304
#define SM_BIAS   106624
#define SM_TOTAL_PERSIST 107136

// ---------------- helpers ----------------
__device__ __forceinline__ uint32_t smem_u32(const void* p) {
    uint32_t a;
    asm("{ .reg .u64 t; cvta.to.shared.u64 t, %1; cvt.u32.u64 %0, t; }" : "=r"(a) : "l"(p));
    return a;
}
__device__ __forceinline__ void ldsm4(uint32_t* r, uint32_t addr) {
    asm volatile("ldmatrix.sync.aligned.m8n8.x4.shared.b16 {%0,%1,%2,%3}, [%4];"
                 : "=r"(r[0]), "=r"(r[1]), "=r"(r[2]), "=r"(r[3]) : "r"(addr));
}
__device__ __forceinline__ void hmma(float* d, const uint32_t* a, const uint32_t* b) {
    asm volatile(
        "mma.sync.aligned.m16n8k16.row.col.f32.f16.f16.f32 "
        "{%0,%1,%2,%3}, {%4,%5,%6,%7}, {%8,%9}, {%0,%1,%2,%3};"
        : "+f"(d[0]), "+f"(d[1]), "+f"(d[2]), "+f"(d[3])
        : "r"(a[0]), "r"(a[1]), "r"(a[2]), "r"(a[3]), "r"(b[0]), "r"(b[1]));
}
__device__ __forceinline__ void cp16(uint32_t dst, const void* src) {
    asm volatile("cp.async.cg.shared.global [%0], [%1], 16;" :: "r"(dst), "l"(src) : "memory");
}
__device__ __forceinline__ void cp_commit() {
    asm volatile("cp.async.commit_group;" ::: "memory");
}
__device__ __forceinline__ void cp_wait1() {
    asm volatile("cp.async.wait_group 1;" ::: "memory");
}
__device__ __forceinline__ void cp_wait0() {
    asm volatile("cp.async.wait_group 0;" ::: "memory");
}
__device__ __forceinline__ float ex2f(float x) {
    float r; asm("ex2.approx.f32 %0, %1;" : "=f"(r) : "f"(x)); return r;
}
__device__ __forceinline__ float rcpf(float x) {
    float r; asm("rcp.approx.f32 %0, %1;" : "=f"(r) : "f"(x)); return r;
}
__device__ __forceinline__ float sigf(float x) {          // 1/(1+e^-x), ~1e-6 rel err
    return rcpf(1.0f + ex2f(-1.4426950408889634f * x));
}
__device__ __forceinline__ float tanhf_fast(float x) {    // 2*sig(2x)-1
    return fmaf(2.0f, rcpf(1.0f + ex2f(-2.8853900817779268f * x)), -1.0f);
}

// ---------------- init ----------------
__global__ void init_kernel() {
    int i = blockIdx.x * blockDim.x + threadIdx.x;
    if (i < NN * BB * HH) {
        g_h0[0][i] = __float2half(0.f);
        g_h1[0][i] = __float2half(0.f);
    }
    if (blockIdx.x == 0 && threadIdx.x < NN) {
        g_cnt2[0][threadIdx.x] = 0u;
        g_cnt2[1][threadIdx.x] = 0u;
        g_ep2[0][threadIdx.x] = 0u;
        g_ep2[1][threadIdx.x] = 0u;
    }
}

// ---------------- all weight fp32 -> fp16 in one launch ----------------
__global__ void __launch_bounds__(256) f2h_all(const float4* __restrict__ w0,
                                               const float4* __restrict__ w1,
                                               const float4* __restrict__ w2,
                                               const float4* __restrict__ w3,
                                               const float4* __restrict__ wh) {
    const long NW = (long)NN * 4 * HH * HH / 4;
    const long NH = (long)NN * MMd * HH / 4;
    long i = (long)blockIdx.x * 256 + threadIdx.x;
    const float4* src; __half2* dst; long o;
    if (i < NW)            { src = w0; dst = (__half2*)g_wih0; o = i; }
    else if (i < 2 * NW)   { src = w1; dst = (__half2*)g_whh0; o = i - NW; }
    else if (i < 3 * NW)   { src = w2; dst = (__half2*)g_wih1; o = i - 2 * NW; }
    else if (i < 4 * NW)   { src = w3; dst = (__half2*)g_whh1; o = i - 3 * NW; }
    else if (i < 4 * NW + NH) { src = wh; dst = (__half2*)g_wh1h; o = i - 4 * NW; }
    else return;
    float4 v = src[o];
    dst[2 * o]     = __floats2half2_rn(v.x, v.y);
    dst[2 * o + 1] = __floats2half2_rn(v.z, v.w);
}

// ---------------- input layer ----------------
__global__ void __launch_bounds__(256) input_kernel(const float* __restrict__ x,
                                                    const float* __restrict__ Win,
                                                    const float* __restrict__ binp) {
    int tok0 = blockIdx.x * 8;
    int tid = threadIdx.x;
    __shared__ float xs[8][DIN];
    for (int i = tid; i < 8 * DIN; i += 256) xs[i >> 6][i & 63] = x[(size_t)tok0 * DIN + i];
    __syncthreads();
    int c0 = tid, c1 = tid + 256;
    float a0[8], a1[8];
#pragma unroll
    for (int k = 0; k < 8; k++) { a0[k] = 0.f; a1[k] = 0.f; }
    const float* w0 = Win + (size_t)c0 * DIN;
    const float* w1 = Win + (size_t)c1 * DIN;
    for (int k = 0; k < DIN; k++) {
        float wv0 = w0[k], wv1 = w1[k];
#pragma unroll
        for (int tk = 0; tk < 8; tk++) {
            a0[tk] += wv0 * xs[tk][k];
            a1[tk] += wv1 * xs[tk][k];
        }
    }
    float bb0 = binp[c0], bb1 = binp[c1];
#pragma unroll
    for (int tk = 0; tk < 8; tk++) {
        float v0 = a0[tk] + bb0;
        v0 = (v0 > 0.f ? v0 : 0.2f * v0) * 10.0f;
        g_z[(size_t)(tok0 + tk) * HH + c0] = __float2half(v0);
        float v1 = a1[tk] + bb1;
        v1 = (v1 > 0.f ? v1 : 0.2f * v1) * 10.0f;
        g_z[(size_t)(tok0 + tk) * HH + c1] = __float2half(v1);
    }
}

// ---------------- persistent wavefront kernel ----------------
// Grid (16, 8, 2): role 0 = layer-0 CTA, role 1 = layer-1 CTA. 256 CTAs, 2/SM.
// Super-step s: role 0 computes l0[t=s] (s<TT); role 1 computes l1[t=s-1] (s>=1).
// A rows gate-interleaved -> register-only gate epilogue; c state + bias in smem.
// compute() double-buffers ldsm fragments across ks-steps to hide LDS latency.
__global__ void __launch_bounds__(256, 2) lstm_persist(const float* __restrict__ b_ih0,
                                                       const float* __restrict__ b_hh0,
                                                       const float* __restrict__ b_ih1,
                                                       const float* __restrict__ b_hh1) {
    extern __shared__ char smem[];
    float* csm    = (float*)(smem + SM_CSM);    // [jlocal*65 + b]
    float* bias_s = (float*)(smem + SM_BIAS);   // [gate*32 + jlocal]
    const int jt = blockIdx.x, n = blockIdx.y, role = blockIdx.z;
    const int tid = threadIdx.x;
    const int wid = tid >> 5, l = tid & 31;
    uint32_t sbase = smem_u32(smem);

    if (tid < 128) {
        int wr = (tid >> 5) * HH + jt * 32 + (tid & 31);
        const float* ba = role ? b_ih1 : b_ih0;
        const float* bb = role ? b_hh1 : b_hh0;
        bias_s[tid] = ba[n * 4 * HH + wr] + bb[n * 4 * HH + wr];
    }
    for (int i = tid; i < 2080; i += 256) csm[i] = 0.f;

    // coalesced loader constants: lane u = tid>>3 picks row-in-band, (tid&7)*16B within row
    const int u = tid >> 3;
    const int lane8 = (tid & 7) * 8;       // halves
    // gate-interleaved A source: band i, band-row u -> gate u>>3, j = jt*32 + i*8 + (u&7)
    int growOff[4];
    uint32_t stsA[4];
#pragma unroll
    for (int i = 0; i < 4; ++i) {
        const int row = i * 32 + u;
        growOff[i] = (((u >> 3) * HH) + jt * 32 + i * 8 + (u & 7)) * HH + lane8;
        stsA[i] = (uint32_t)(row * 128 + (((tid & 7) * 16) ^ ((row & 7) << 4)));
    }
    uint32_t stsB[2];
#pragma unroll
    for (int i = 0; i < 2; ++i) {
        const int row = i * 32 + u;
        stsB[i] = (uint32_t)(row * 128 + (((tid & 7) * 16) ^ ((row & 7) << 4)));
    }
    const int b0 = u, b1 = 32 + u;
    const int hOff0 = (n * BB + b0) * HH + lane8;
    const int hOff1 = (n * BB + b1) * HH + lane8;

    const __half* Wi = (role ? g_wih1 : g_wih0) + (size_t)n * 4 * HH * HH;
    const __half* Wh = (role ? g_whh1 : g_whh0) + (size_t)n * 4 * HH * HH;

    // fragment mappings (32x32 warp tiles: wm = wid&3 rows, wn = wid>>2 cols)
    const int wm = wid & 3, wn = wid >> 2;
    const int wnB = wn * 32;
    const int arow0 = wm * 32 + (l & 15);
    const int aunit = (l >> 4) & 1;
    const int brow0 = wnB + (l & 7) + ((l >> 4) & 1) * 8;
    const int bunit = (l >> 3) & 1;

    // epilogue coordinates
    const int jlocal = wm * 8 + (l >> 2);
    const int jcol = jt * 32 + jlocal;

    auto issueA = [&](int c) {   // A half-chunk: 32KB across CTA
        const __half* srcA = (c < 4) ? Wi : Wh;
        const int kh = (c & 3) * 128;
        const uint32_t sA = sbase + SMA(c & 1);
#pragma unroll
        for (int p = 0; p < 8; ++p) {
            const int q = p >> 2, i = p & 3;
            cp16(sA + q * 16384 + stsA[i], srcA + growOff[i] + kh + q * 64);
        }
    };
    auto issueB = [&](int c, const __half* r0, const __half* r1) {   // B: 16KB across CTA
        const int kh = (c & 3) * 128;
        const uint32_t sB = sbase + SMB(c & 1);
#pragma unroll
        for (int p = 0; p < 4; ++p) {
            const int q = p >> 1, i = p & 1;
            cp16(sB + q * 8192 + stsB[i], (i ? r1 : r0) + kh + q * 64);
        }
    };

    // initial prefetch for first active phase
    if (role == 0) {
        const __half* z0 = g_z + ((size_t)b0 * TT + 0) * HH + lane8;
        const __half* z1 = g_z + ((size_t)b1 * TT + 0) * HH + lane8;
        issueA(0); issueB(0, z0, z1); cp_commit();
        issueA(1); issueB(1, z0, z1); cp_commit();
    } else {
        issueA(0); cp_commit();
        issueA(1); cp_commit();
    }
    __syncthreads();   // bias_s + csm ready (also covers smem init vs first epilogue)

#pragma unroll 1
    for (int s = 0; s <= TT; ++s) {
        const bool active = role == 0 ? (s < TT) : (s >= 1);
        if (active) {
            const int t = role == 0 ? s : s - 1;
            const __half *L0, *L1, *H0, *H1;
            __half* Hout;
            if (role == 0) {
                L0 = g_z + ((size_t)b0 * TT + t) * HH + lane8;
                L1 = g_z + ((size_t)b1 * TT + t) * HH + lane8;
                H0 = g_h0[t & 3] + hOff0;  H1 = g_h0[t & 3] + hOff1;
                Hout = g_h0[(t + 1) & 3];
            } else {
                L0 = g_h0[(t + 1) & 3] + hOff0;  L1 = g_h0[(t + 1) & 3] + hOff1;
                H0 = g_h1[t & 1] + hOff0;        H1 = g_h1[t & 1] + hOff1;
                Hout = g_h1[(t + 1) & 1];
                // role1's B for chunks 0,1 depends on the barrier -> issue now
                issueB(0, L0, L1); cp_commit();
                issueB(1, L0, L1); cp_commit();
            }

            float acc[2][4][4];
#pragma unroll
            for (int i = 0; i < 2; i++)
#pragma unroll
                for (int j = 0; j < 4; j++)
#pragma unroll
                    for (int k = 0; k < 4; k++) acc[i][j][k] = 0.f;

            // compute with fragment double-buffering across the 8 ks-steps of a chunk
            auto compute = [&](int st) {
                const uint32_t Ab = sbase + SMA(st);
                const uint32_t Bb = sbase + SMB(st);
                uint32_t afr[2][2][4], bfr[2][2][4];
                auto loadfrag = [&](int i, int buf) {
                    const int q = i >> 2, ksl = i & 3;
#pragma unroll
                    for (int mi = 0; mi < 2; ++mi) {
                        const int row = arow0 + mi * 16;
                        const uint32_t off = ((uint32_t)((ksl * 2 + aunit) * 16)) ^ ((uint32_t)((row & 7) << 4));
                        ldsm4(afr[buf][mi], Ab + (uint32_t)(q * 16384 + row * 128) + off);
                    }
#pragma unroll
                    for (int cb = 0; cb < 2; ++cb) {
                        const int col = brow0 + cb * 16;
                        const uint32_t off = ((uint32_t)((ksl * 2 + bunit) * 16)) ^ ((uint32_t)((col & 7) << 4));
                        ldsm4(bfr[buf][cb], Bb + (uint32_t)(q * 8192 + col * 128) + off);
                    }
                };
                loadfrag(0, 0);
#pragma unroll
                for (int i = 0; i < 8; ++i) {
                    if (i < 7) loadfrag(i + 1, (i + 1) & 1);
                    const int buf = i & 1;
#pragma unroll
                    for (int mi = 0; mi < 2; ++mi)
#pragma unroll
                        for (int nt = 0; nt < 4; ++nt)
                            hmma(acc[mi][nt], afr[buf][mi], &bfr[buf][nt >> 1][(nt & 1) * 2]);
                }
            };

#pragma unroll 1
            for (int c = 0; c < 8; ++c) {
                if (c < 7) cp_wait1(); else cp_wait0();
                __syncthreads();
                compute(c & 1);
                __syncthreads();
                if (c + 2 < 8) {
                    const int cn = c + 2;
                    issueA(cn);
                    if (cn < 4) issueB(cn, L0, L1);
                    else        issueB(cn, H0, H1);
                    cp_commit();
                }
            }

            // next-phase prefetch (loads start under epilogue + barrier spin)
            if (role == 0) {
                if (s + 1 < TT) {
                    const __half* z0 = g_z + ((size_t)b0 * TT + (s + 1)) * HH + lane8;
                    const __half* z1 = g_z + ((size_t)b1 * TT + (s + 1)) * HH + lane8;
                    issueA(0); issueB(0, z0, z1); cp_commit();
                    issueA(1); issueB(1, z0, z1); cp_commit();
                }
            } else {
                if (s < TT) {
                    issueA(0); cp_commit();
                    issueA(1); cp_commit();
                }
            }

            // epilogue: gates in regs, c in smem (thread-owned slots, no sync needed)
            const float bg0 = bias_s[jlocal];
            const float bg1 = bias_s[32 + jlocal];
            const float bg2 = bias_s[64 + jlocal];
            const float bg3 = bias_s[96 + jlocal];
#pragma unroll
            for (int nt = 0; nt < 4; ++nt) {
#pragma unroll
                for (int e = 0; e < 2; ++e) {
                    const int b = wnB + nt * 8 + 2 * (l & 3) + e;
                    const int ci = jlocal * 65 + b;
                    float gi = acc[0][nt][e]     + bg0;
                    float gf = acc[0][nt][2 + e] + bg1;
                    float gg = acc[1][nt][e]     + bg2;
                    float go = acc[1][nt][2 + e] + bg3;
                    float cn = sigf(gf) * csm[ci] + sigf(gi) * tanhf_fast(gg);
                    float hn = sigf(go) * tanhf_fast(cn);
                    csm[ci] = cn;
                    Hout[(n * BB + b) * HH + jcol] = __float2half(hn);
                    if (role) g_y[((size_t)(n * BB + b) * TT + t) * HH + jcol] = __float2half(hn);
                }
            }
        }

        // ---- split per-role barrier ----
        if (s < TT) {
            __threadfence();   // publish h stores before arrive
            if (tid == 0) {
                if (atomicAdd(&g_cnt2[role][n], 1u) == 15u) {
                    g_cnt2[role][n] = 0u;
                    __threadfence();
                    atomicAdd(&g_ep2[role][n], 1u);
                }
                volatile unsigned* ep0 = &g_ep2[0][n];
                volatile unsigned* ep1 = &g_ep2[1][n];
                const int ns = s + 1;   // next super-step
                if (role == 0) {
                    if (ns < TT) {
                        while ((int)*ep0 < ns) { }
                        while ((int)*ep1 < ns - 2) { }
                    }
                } else {
                    while ((int)*ep1 < ns) { }
                    while ((int)*ep0 < ns) { }
                }
            }
            __syncthreads();
        }
    }
}

// ---------------- fused head (unchanged, known-good) ----------------
__global__ void __launch_bounds__(256) head_kernel(const float* __restrict__ bh1,
                                                   const float* __restrict__ Wh2,
                                                   const float* __restrict__ bh2,
                                                   float* __restrict__ out) {
    extern __shared__ char smem[];
    const int n = blockIdx.y;
    const int rt = blockIdx.x;
    const int b = rt >> 2;
    const int t0 = (rt & 3) * 64;
    const int tid = threadIdx.x;
    const int wid = tid >> 5, l = tid & 31;
    const int wm = wid & 3, wn = wid >> 2;
    uint32_t sbase = smem_u32(smem);

    const int am = tid >> 2, akw = (tid & 3) * 2;
    const __half* ybase = g_y + ((size_t)((n * BB + b) * TT) + t0 + am) * HH;
    uint32_t a_sts[2];
#pragma unroll
    for (int i = 0; i < 2; i++) a_sts[i] = (uint32_t)((am * 128 + (akw + i) * 16) ^ ((((am * 128 + (akw + i) * 16) >> 3) & 0x70)));
    const int bmr = tid >> 1, bkw = (tid & 1) * 4;
    uint32_t b_sts[4];
#pragma unroll
    for (int i = 0; i < 4; i++) b_sts[i] = (uint32_t)((bmr * 128 + (bkw + i) * 16) ^ ((((bmr * 128 + (bkw + i) * 16) >> 3) & 0x70)));

    const int arow = wm * 16 + (l & 7) + ((l >> 3) & 1) * 8;
    const uint32_t a_rb = (uint32_t)arow * 128u;
    const uint32_t a_swz = (uint32_t)((arow & 7) << 4);
    const uint32_t akbx = (uint32_t)(((l >> 4) & 1) * 16);
    const int brb = (l & 7) + ((l >> 4) & 1) * 8;
    const uint32_t bkbx = (uint32_t)(((l >> 3) & 1) * 16);

    float o0 = 0.f, o1 = 0.f;
    const int p0 = tid * 2, p1 = tid * 2 + 1;
    const int r0 = p0 / 7, q0 = p0 % 7;
    const int r1 = p1 / 7, q1 = p1 % 7;
    const bool act = (p0 < 64 * OO);

    float* hsm = (float*)smem;

#pragma unroll 1
    for (int mt = 0; mt < 4; ++mt) {
        const int m0 = mt * 128;
        const __half* wbase = g_wh1h + ((size_t)(n * MMd) + m0 + bmr) * HH;

        uint4 ra[2], rb[4];
        auto fetch = [&](int kc) {
#pragma unroll
            for (int i = 0; i < 2; i++) ra[i] = *(const uint4*)(ybase + kc * 64 + (akw + i) * 8);
#pragma unroll
            for (int i = 0; i < 4; i++) rb[i] = *(const uint4*)(wbase + kc * 64 + (bkw + i) * 8);
        };
        auto store_stage = [&](int s) {
            char* Ab = smem + s * 8192;
            char* Bb = smem + 16384 + s * 16384;
#pragma unroll
            for (int i = 0; i < 2; i++) *(uint4*)(Ab + a_sts[i]) = ra[i];
#pragma unroll
            for (int i = 0; i < 4; i++) *(uint4*)(Bb + b_sts[i]) = rb[i];
        };

        float acc[8][4];
#pragma unroll
        for (int i = 0; i < 8; i++)
#pragma unroll
            for (int j = 0; j < 4; j++) acc[i][j] = 0.f;

        auto compute = [&](int s) {
            uint32_t Ab = sbase + s * 8192;
            uint32_t Bb = sbase + 16384 + s * 16384;
#pragma unroll
            for (int ks = 0; ks < 4; ++ks) {
                uint32_t a[4];
                ldsm4(a, Ab + a_rb + (((uint32_t)(ks * 32) + akbx) ^ a_swz));
                uint32_t bfr[16];
#pragma unroll
                for (int p = 0; p < 4; ++p) {
                    int br = wn * 64 + p * 16 + brb;
                    ldsm4(&bfr[p * 4],
                          Bb + (uint32_t)br * 128 + (((uint32_t)(ks * 32) + bkbx) ^ (uint32_t)((br & 7) << 4)));
                }
#pragma unroll
                for (int nt = 0; nt < 8; ++nt) hmma(acc[nt], a, &bfr[nt * 2]);
            }
        };

        fetch(0);
        store_stage(0);
        fetch(1);
        __syncthreads();
#pragma unroll 1
        for (int kc = 0; kc < 8; ++kc) {
            if (kc < 7) store_stage((kc + 1) & 1);
            if (kc < 6) fetch(kc + 2);
            compute(kc & 1);
            __syncthreads();
        }

        {
            int r = wm * 16 + (l >> 2);
            int cc = (l & 3) * 2;
#pragma unroll
            for (int nt = 0; nt < 8; ++nt) {
                int col = wn * 64 + nt * 8 + cc;
                float bia = bh1[n * MMd + m0 + col];
                float bib = bh1[n * MMd + m0 + col + 1];
                float v0 = acc[nt][0] + bia, v1 = acc[nt][1] + bib;
                float v2 = acc[nt][2] + bia, v3 = acc[nt][3] + bib;
                hsm[r * 132 + col]           = (v0 > 0.f ? v0 : 0.2f * v0);
                hsm[r * 132 + col + 1]       = (v1 > 0.f ? v1 : 0.2f * v1);
                hsm[(r + 8) * 132 + col]     = (v2 > 0.f ? v2 : 0.2f * v2);
                hsm[(r + 8) * 132 + col + 1] = (v3 > 0.f ? v3 : 0.2f * v3);
            }
        }
        __syncthreads();
        if (act) {
            const float* w2a = Wh2 + (size_t)(n * OO + q0) * MMd + m0;
            const float* w2b = Wh2 + (size_t)(n * OO + q1) * MMd + m0;
            float s0 = 0.f, s1 = 0.f;
#pragma unroll 4
            for (int mm = 0; mm < 128; ++mm) {
                s0 += hsm[r0 * 132 + mm] * w2a[mm];
                s1 += hsm[r1 * 132 + mm] * w2b[mm];
            }
            o0 += s0;
            o1 += s1;
        }
        __syncthreads();
    }
    if (act) {
        out[((size_t)(n * BB + b) * TT + (t0 + r0)) * OO + q0] = o0 + bh2[n * OO + q0];
        out[((size_t)(n * BB + b) * TT + (t0 + r1)) * OO + q1] = o1 + bh2[n * OO + q1];
    }
}

// ---------------- launch ----------------
extern "C" void kernel_launch(void* const* d_in, const int* in_sizes, int n_in,
                              void* d_out, int out_size) {
    const float* x     = (const float*)d_in[0];
    const float* Win   = (const float*)d_in[1];
    const float* binp  = (const float*)d_in[2];
    const float* W_ih0 = (const float*)d_in[3];
    const float* W_hh0 = (const float*)d_in[4];
    const float* b_ih0 = (const float*)d_in[5];
    const float* b_hh0 = (const float*)d_in[6];
    const float* W_ih1 = (const float*)d_in[7];
    const float* W_hh1 = (const float*)d_in[8];
    const float* b_ih1 = (const float*)d_in[9];
    const float* b_hh1 = (const float*)d_in[10];
    const float* Wh1   = (const float*)d_in[11];
    const float* bh1   = (const float*)d_in[12];
    const float* Wh2   = (const float*)d_in[13];
    const float* bh2   = (const float*)d_in[14];
    float* out = (float*)d_out;

    cudaFuncSetAttribute(lstm_persist, cudaFuncAttributeMaxDynamicSharedMemorySize, SM_TOTAL_PERSIST);

    // 2 hidden harness launches + these 3 => lstm_persist is profiled launch #6 (-s 5 -c 1)
    init_kernel<<<(NN * BB * HH + 255) / 256, 256>>>();
    input_kernel<<<(BB * TT) / 8, 256>>>(x, Win, binp);
    {
        const long total4 = 4L * (NN * 4 * HH * HH / 4) + (NN * MMd * HH / 4);
        f2h_all<<<(int)((total4 + 255) / 256), 256>>>((const float4*)W_ih0, (const float4*)W_hh0,
                                                      (const float4*)W_ih1, (const float4*)W_hh1,
                                                      (const float4*)Wh1);
    }

    lstm_persist<<<dim3(16, NN, 2), 256, SM_TOTAL_PERSIST>>>(b_ih0, b_hh0, b_ih1, b_hh1);

    head_kernel<<<dim3(256, NN), 256, 49152>>>(bh1, Wh2, bh2, out);
}

// round 15
// speedup vs baseline: 1.0615x; 1.0615x over previous
#include <cuda_runtime.h>
#include <cuda_fp16.h>
#include <math.h>
#include <cstdint>

#define NN 8
#define BB 64
#define TT 256
#define DIN 64
#define HH 512
#define MMd 512
#define OO 7

// ---------------- device globals (no allocation allowed) ----------------
__device__ __half g_z[BB * TT * HH];                 // input-layer output, fp16, [b][t][H]
__device__ __half g_h0[4][NN * BB * HH];             // 4-deep h0 ring
__device__ __half g_h1z[NN * BB * HH];               // zeros (h1 at t=-1); never written
__device__ __half g_y[(size_t)NN * BB * TT * HH];    // layer-1 outputs (= h1 history), fp16
__device__ __half g_wih0[NN * 4 * HH * HH];          // fp16 weight copies
__device__ __half g_whh0[NN * 4 * HH * HH];
__device__ __half g_wih1[NN * 4 * HH * HH];
__device__ __half g_whh1[NN * 4 * HH * HH];
__device__ __half g_wh1h[NN * MMd * HH];             // head Wh1 fp16

// monotonic per-role, per-ensemble barrier counters (16 CTAs per group)
__device__ unsigned g_ctr[2][NN];

// persist smem layout (dynamic):
//   A stage s: @ s*32768, 32KB each = 2 subs x [128 rows][128B] swizzled
//   B stage s: @ 65536 + s*16384, 16KB each = 2 subs x [64 rows][128B]
//   bias float[128] @ 98304 ; total 99328.
#define SMA(s)   ((s) * 32768)
#define SMB(s)   (65536 + (s) * 16384)
#define SM_BIAS  98304
#define SM_TOTAL_PERSIST 99328

// ---------------- helpers ----------------
__device__ __forceinline__ uint32_t smem_u32(const void* p) {
    uint32_t a;
    asm("{ .reg .u64 t; cvta.to.shared.u64 t, %1; cvt.u32.u64 %0, t; }" : "=r"(a) : "l"(p));
    return a;
}
__device__ __forceinline__ void ldsm4(uint32_t* r, uint32_t addr) {
    asm volatile("ldmatrix.sync.aligned.m8n8.x4.shared.b16 {%0,%1,%2,%3}, [%4];"
                 : "=r"(r[0]), "=r"(r[1]), "=r"(r[2]), "=r"(r[3]) : "r"(addr));
}
__device__ __forceinline__ void hmma(float* d, const uint32_t* a, const uint32_t* b) {
    asm volatile(
        "mma.sync.aligned.m16n8k16.row.col.f32.f16.f16.f32 "
        "{%0,%1,%2,%3}, {%4,%5,%6,%7}, {%8,%9}, {%0,%1,%2,%3};"
        : "+f"(d[0]), "+f"(d[1]), "+f"(d[2]), "+f"(d[3])
        : "r"(a[0]), "r"(a[1]), "r"(a[2]), "r"(a[3]), "r"(b[0]), "r"(b[1]));
}
__device__ __forceinline__ void cp16(uint32_t dst, const void* src) {
    asm volatile("cp.async.cg.shared.global [%0], [%1], 16;" :: "r"(dst), "l"(src) : "memory");
}
__device__ __forceinline__ void cp_commit() {
    asm volatile("cp.async.commit_group;" ::: "memory");
}
__device__ __forceinline__ void cp_wait1() {
    asm volatile("cp.async.wait_group 1;" ::: "memory");
}
__device__ __forceinline__ void cp_wait0() {
    asm volatile("cp.async.wait_group 0;" ::: "memory");
}
__device__ __forceinline__ float ex2f(float x) {
    float r; asm("ex2.approx.f32 %0, %1;" : "=f"(r) : "f"(x)); return r;
}
__device__ __forceinline__ float rcpf(float x) {
    float r; asm("rcp.approx.f32 %0, %1;" : "=f"(r) : "f"(x)); return r;
}
__device__ __forceinline__ float sigf(float x) {          // 1/(1+e^-x), ~1e-6 rel err
    return rcpf(1.0f + ex2f(-1.4426950408889634f * x));
}
__device__ __forceinline__ float tanhf_fast(float x) {    // 2*sig(2x)-1
    return fmaf(2.0f, rcpf(1.0f + ex2f(-2.8853900817779268f * x)), -1.0f);
}

// ---------------- init ----------------
__global__ void init_kernel() {
    int i = blockIdx.x * blockDim.x + threadIdx.x;
    if (i < NN * BB * HH) {
        g_h0[0][i] = __float2half(0.f);   // h0_{-1}; other slots written before read
    }
    if (blockIdx.x == 0 && threadIdx.x < 2 * NN) {
        g_ctr[threadIdx.x >> 3][threadIdx.x & 7] = 0u;
    }
}

// ---------------- all weight fp32 -> fp16 in one launch ----------------
__global__ void __launch_bounds__(256) f2h_all(const float4* __restrict__ w0,
                                               const float4* __restrict__ w1,
                                               const float4* __restrict__ w2,
                                               const float4* __restrict__ w3,
                                               const float4* __restrict__ wh) {
    const long NW = (long)NN * 4 * HH * HH / 4;
    const long NH = (long)NN * MMd * HH / 4;
    long i = (long)blockIdx.x * 256 + threadIdx.x;
    const float4* src; __half2* dst; long o;
    if (i < NW)            { src = w0; dst = (__half2*)g_wih0; o = i; }
    else if (i < 2 * NW)   { src = w1; dst = (__half2*)g_whh0; o = i - NW; }
    else if (i < 3 * NW)   { src = w2; dst = (__half2*)g_wih1; o = i - 2 * NW; }
    else if (i < 4 * NW)   { src = w3; dst = (__half2*)g_whh1; o = i - 3 * NW; }
    else if (i < 4 * NW + NH) { src = wh; dst = (__half2*)g_wh1h; o = i - 4 * NW; }
    else return;
    float4 v = src[o];
    dst[2 * o]     = __floats2half2_rn(v.x, v.y);
    dst[2 * o + 1] = __floats2half2_rn(v.z, v.w);
}

// ---------------- input layer ----------------
__global__ void __launch_bounds__(256) input_kernel(const float* __restrict__ x,
                                                    const float* __restrict__ Win,
                                                    const float* __restrict__ binp) {
    int tok0 = blockIdx.x * 8;
    int tid = threadIdx.x;
    __shared__ float xs[8][DIN];
    for (int i = tid; i < 8 * DIN; i += 256) xs[i >> 6][i & 63] = x[(size_t)tok0 * DIN + i];
    __syncthreads();
    int c0 = tid, c1 = tid + 256;
    float a0[8], a1[8];
#pragma unroll
    for (int k = 0; k < 8; k++) { a0[k] = 0.f; a1[k] = 0.f; }
    const float* w0 = Win + (size_t)c0 * DIN;
    const float* w1 = Win + (size_t)c1 * DIN;
    for (int k = 0; k < DIN; k++) {
        float wv0 = w0[k], wv1 = w1[k];
#pragma unroll
        for (int tk = 0; tk < 8; tk++) {
            a0[tk] += wv0 * xs[tk][k];
            a1[tk] += wv1 * xs[tk][k];
        }
    }
    float bb0 = binp[c0], bb1 = binp[c1];
#pragma unroll
    for (int tk = 0; tk < 8; tk++) {
        float v0 = a0[tk] + bb0;
        v0 = (v0 > 0.f ? v0 : 0.2f * v0) * 10.0f;
        g_z[(size_t)(tok0 + tk) * HH + c0] = __float2half(v0);
        float v1 = a1[tk] + bb1;
        v1 = (v1 > 0.f ? v1 : 0.2f * v1) * 10.0f;
        g_z[(size_t)(tok0 + tk) * HH + c1] = __float2half(v1);
    }
}

// ---------------- persistent wavefront kernel ----------------
// Grid (16, 8, 2): role 0 = layer-0 CTA, role 1 = layer-1 CTA. 256 CTAs, 2/SM.
// Role 0 at step s computes l0[t=s] (s<TT).
// Role 1 LAGS 2: at step s computes l1[t=s-2] (s>=2), reading h0_t (certified one
// barrier early -> pre-barrier prefetch, no cold restart) and h1_{t-1} = y[t-1].
// Chunk halves: role0 lo=(Wih0, z_t) hi=(Whh0, h0_{t-1}); role1 lo=(Wih1, h0_t)
// hi=(Whh1, y[t-1]).  A rows gate-interleaved -> register-only cell epilogue.
__global__ void __launch_bounds__(256, 2) lstm_persist(const float* __restrict__ b_ih0,
                                                       const float* __restrict__ b_hh0,
                                                       const float* __restrict__ b_ih1,
                                                       const float* __restrict__ b_hh1) {
    extern __shared__ char smem[];
    float* bias_s = (float*)(smem + SM_BIAS);
    const int jt = blockIdx.x, n = blockIdx.y, role = blockIdx.z;
    const int tid = threadIdx.x;
    const int wid = tid >> 5, l = tid & 31;
    uint32_t sbase = smem_u32(smem);

    if (tid < 128) {
        int wr = (tid >> 5) * HH + jt * 32 + (tid & 31);
        const float* ba = role ? b_ih1 : b_ih0;
        const float* bb = role ? b_hh1 : b_hh0;
        bias_s[tid] = ba[n * 4 * HH + wr] + bb[n * 4 * HH + wr];
    }

    // coalesced loader constants: lane u = tid>>3 picks row-in-band, (tid&7)*16B within row
    const int u = tid >> 3;
    const int lane8 = (tid & 7) * 8;       // halves
    // gate-interleaved A source: band i, band-row u -> gate u>>3, j = jt*32 + i*8 + (u&7)
    int growOff[4];
    uint32_t stsA[4];
#pragma unroll
    for (int i = 0; i < 4; ++i) {
        const int row = i * 32 + u;
        growOff[i] = (((u >> 3) * HH) + jt * 32 + i * 8 + (u & 7)) * HH + lane8;
        stsA[i] = (uint32_t)(row * 128 + (((tid & 7) * 16) ^ ((row & 7) << 4)));
    }
    uint32_t stsB[2];
#pragma unroll
    for (int i = 0; i < 2; ++i) {
        const int row = i * 32 + u;
        stsB[i] = (uint32_t)(row * 128 + (((tid & 7) * 16) ^ ((row & 7) << 4)));
    }
    const int b0 = u, b1 = 32 + u;
    const int hOff0 = (n * BB + b0) * HH + lane8;
    const int hOff1 = (n * BB + b1) * HH + lane8;

    // A weight streams per role (lo = chunks 0-3, hi = chunks 4-7)
    const __half* A_lo = (role ? g_wih1 : g_wih0) + (size_t)n * 4 * HH * HH;
    const __half* A_hi = (role ? g_whh1 : g_whh0) + (size_t)n * 4 * HH * HH;

    // fragment mappings (32x32 warp tiles: wm = wid&3 rows, wn = wid>>2 cols)
    const int wm = wid & 3, wn = wid >> 2;
    const int wnB = wn * 32;
    const int arow0 = wm * 32 + (l & 15);
    const int aunit = (l >> 4) & 1;
    const int brow0 = wnB + (l & 7) + ((l >> 4) & 1) * 8;
    const int bunit = (l >> 3) & 1;

    // epilogue coordinates: jcol fixed, 8 b-values
    const int jcol = jt * 32 + wm * 8 + (l >> 2);
    float bias_g[4];
    {
        const float* ba = role ? b_ih1 : b_ih0;
        const float* bb = role ? b_hh1 : b_hh0;
#pragma unroll
        for (int g = 0; g < 4; ++g) {
            const int wr = n * 4 * HH + g * HH + jcol;
            bias_g[g] = ba[wr] + bb[wr];
        }
    }

    float c_reg[8];
#pragma unroll
    for (int k = 0; k < 8; ++k) c_reg[k] = 0.f;

    auto issueA = [&](int c) {   // A half-chunk: 32KB across CTA
        const __half* srcA = (c < 4) ? A_lo : A_hi;
        const int kh = (c & 3) * 128;
        const uint32_t sA = sbase + SMA(c & 1);
#pragma unroll
        for (int p = 0; p < 8; ++p) {
            const int q = p >> 2, i = p & 3;
            cp16(sA + q * 16384 + stsA[i], srcA + growOff[i] + kh + q * 64);
        }
    };
    auto issueB = [&](int c, const __half* r0, const __half* r1) {   // B: 16KB across CTA
        const int kh = (c & 3) * 128;
        const uint32_t sB = sbase + SMB(c & 1);
#pragma unroll
        for (int p = 0; p < 4; ++p) {
            const int q = p >> 1, i = p & 1;
            cp16(sB + q * 8192 + stsB[i], (i ? r1 : r0) + kh + q * 64);
        }
    };

    __syncthreads();   // bias_s ready

    // initial prefetch: role0 -> chunks 0,1 of phase t=0 (A + z). role1: nothing
    // (its first active phase is s=2; prefetch happens at end of s=1).
    if (role == 0) {
        const __half* z0 = g_z + ((size_t)b0 * TT + 0) * HH + lane8;
        const __half* z1 = g_z + ((size_t)b1 * TT + 0) * HH + lane8;
        issueA(0); issueB(0, z0, z1); cp_commit();
        issueA(1); issueB(1, z0, z1); cp_commit();
    }

#pragma unroll 1
    for (int s = 0; s <= TT + 1; ++s) {
        const bool active = role == 0 ? (s < TT) : (s >= 2);
        if (active) {
            const int t = role == 0 ? s : s - 2;
            const __half *L0, *L1, *H0, *H1;
            __half* Hout = 0;
            if (role == 0) {
                L0 = g_z + ((size_t)b0 * TT + t) * HH + lane8;
                L1 = g_z + ((size_t)b1 * TT + t) * HH + lane8;
                H0 = g_h0[t & 3] + hOff0;  H1 = g_h0[t & 3] + hOff1;   // h0_{t-1}
                Hout = g_h0[(t + 1) & 3];
            } else {
                L0 = g_h0[(t + 1) & 3] + hOff0;  L1 = g_h0[(t + 1) & 3] + hOff1;   // h0_t
                if (t == 0) {
                    H0 = g_h1z + hOff0;  H1 = g_h1z + hOff1;
                } else {
                    H0 = g_y + ((size_t)((n * BB + b0) * TT) + (t - 1)) * HH + lane8;
                    H1 = g_y + ((size_t)((n * BB + b1) * TT) + (t - 1)) * HH + lane8;
                }
            }

            float acc[2][4][4];
#pragma unroll
            for (int i = 0; i < 2; i++)
#pragma unroll
                for (int j = 0; j < 4; j++)
#pragma unroll
                    for (int k = 0; k < 4; k++) acc[i][j][k] = 0.f;

            auto compute = [&](int st) {
                const uint32_t Ab = sbase + SMA(st);
                const uint32_t Bb = sbase + SMB(st);
#pragma unroll
                for (int ks = 0; ks < 8; ++ks) {
                    const int q = ks >> 2, ksl = ks & 3;
                    uint32_t afr[2][4], bfr[2][4];
#pragma unroll
                    for (int mi = 0; mi < 2; ++mi) {
                        const int row = arow0 + mi * 16;
                        const uint32_t off = ((uint32_t)((ksl * 2 + aunit) * 16)) ^ ((uint32_t)((row & 7) << 4));
                        ldsm4(afr[mi], Ab + (uint32_t)(q * 16384 + row * 128) + off);
                    }
#pragma unroll
                    for (int cb = 0; cb < 2; ++cb) {
                        const int col = brow0 + cb * 16;
                        const uint32_t off = ((uint32_t)((ksl * 2 + bunit) * 16)) ^ ((uint32_t)((col & 7) << 4));
                        ldsm4(bfr[cb], Bb + (uint32_t)(q * 8192 + col * 128) + off);
                    }
#pragma unroll
                    for (int mi = 0; mi < 2; ++mi)
#pragma unroll
                        for (int nt = 0; nt < 4; ++nt)
                            hmma(acc[mi][nt], afr[mi], &bfr[nt >> 1][(nt & 1) * 2]);
                }
            };

#pragma unroll 1
            for (int c = 0; c < 8; ++c) {
                if (c < 7) cp_wait1(); else cp_wait0();
                __syncthreads();
                compute(c & 1);
                __syncthreads();
                if (c + 2 < 8) {
                    const int cn = c + 2;
                    issueA(cn);
                    if (cn < 4) issueB(cn, L0, L1);
                    else        issueB(cn, H0, H1);
                    cp_commit();
                }
            }

            // role0 next-phase prefetch (z is barrier-independent)
            if (role == 0 && s + 1 < TT) {
                const __half* z0 = g_z + ((size_t)b0 * TT + (s + 1)) * HH + lane8;
                const __half* z1 = g_z + ((size_t)b1 * TT + (s + 1)) * HH + lane8;
                issueA(0); issueB(0, z0, z1); cp_commit();
                issueA(1); issueB(1, z0, z1); cp_commit();
            }

            // register-only epilogue: acc[0][nt][e]=i, acc[0][nt][2+e]=f,
            // acc[1][nt][e]=g, acc[1][nt][2+e]=o, for b = wnB + nt*8 + 2*(l&3) + e
#pragma unroll
            for (int nt = 0; nt < 4; ++nt) {
#pragma unroll
                for (int e = 0; e < 2; ++e) {
                    const int k = nt * 2 + e;
                    const int b = wnB + nt * 8 + 2 * (l & 3) + e;
                    float gi = acc[0][nt][e]     + bias_g[0];
                    float gf = acc[0][nt][2 + e] + bias_g[1];
                    float gg = acc[1][nt][e]     + bias_g[2];
                    float go = acc[1][nt][2 + e] + bias_g[3];
                    float cn = sigf(gf) * c_reg[k] + sigf(gi) * tanhf_fast(gg);
                    float hn = sigf(go) * tanhf_fast(cn);
                    c_reg[k] = cn;
                    if (role == 0)
                        Hout[(n * BB + b) * HH + jcol] = __float2half(hn);
                    else
                        g_y[((size_t)(n * BB + b) * TT + t) * HH + jcol] = __float2half(hn);
                }
            }
        }

        // role1 pre-barrier prefetch for step s+1 (t' = s-1): A_lo + B_lo = h0_{s-1},
        // which is certified by ctr0 >= 16*s (held since entering step s).
        if (role == 1 && s >= 1 && s <= TT) {
            const __half* p0 = g_h0[s & 3] + hOff0;   // h0_{s-1} lives at slot s&3
            const __half* p1 = g_h0[s & 3] + hOff1;
            issueA(0); issueB(0, p0, p1); cp_commit();
            issueA(1); issueB(1, p0, p1); cp_commit();
        }

        // ---- barrier (monotonic counters) ----
        if (s <= TT) {
            __threadfence();   // publish h0/y stores before arrive
            if (tid == 0) {
                atomicAdd(&g_ctr[role][n], 1u);
                const unsigned ns = (unsigned)(s + 1);
                volatile unsigned* c0 = &g_ctr[0][n];
                volatile unsigned* c1 = &g_ctr[1][n];
                if (role == 0) {
                    if (ns < TT) {
                        while (*c0 < 16u * ns) { }
                        while (*c1 < 16u * (ns - 1)) { }   // h0 ring depth 4, role1 lag 2
                    }
                } else {
                    while (*c1 < 16u * ns) { }
                    while (*c0 < 16u * ns) { }             // makes h0 prefetch safe next step
                }
            }
            __syncthreads();
        }
    }
}

// ---------------- fused head (unchanged, known-good) ----------------
__global__ void __launch_bounds__(256) head_kernel(const float* __restrict__ bh1,
                                                   const float* __restrict__ Wh2,
                                                   const float* __restrict__ bh2,
                                                   float* __restrict__ out) {
    extern __shared__ char smem[];
    const int n = blockIdx.y;
    const int rt = blockIdx.x;
    const int b = rt >> 2;
    const int t0 = (rt & 3) * 64;
    const int tid = threadIdx.x;
    const int wid = tid >> 5, l = tid & 31;
    const int wm = wid & 3, wn = wid >> 2;
    uint32_t sbase = smem_u32(smem);

    const int am = tid >> 2, akw = (tid & 3) * 2;
    const __half* ybase = g_y + ((size_t)((n * BB + b) * TT) + t0 + am) * HH;
    uint32_t a_sts[2];
#pragma unroll
    for (int i = 0; i < 2; i++) a_sts[i] = (uint32_t)((am * 128 + (akw + i) * 16) ^ ((((am * 128 + (akw + i) * 16) >> 3) & 0x70)));
    const int bmr = tid >> 1, bkw = (tid & 1) * 4;
    uint32_t b_sts[4];
#pragma unroll
    for (int i = 0; i < 4; i++) b_sts[i] = (uint32_t)((bmr * 128 + (bkw + i) * 16) ^ ((((bmr * 128 + (bkw + i) * 16) >> 3) & 0x70)));

    const int arow = wm * 16 + (l & 7) + ((l >> 3) & 1) * 8;
    const uint32_t a_rb = (uint32_t)arow * 128u;
    const uint32_t a_swz = (uint32_t)((arow & 7) << 4);
    const uint32_t akbx = (uint32_t)(((l >> 4) & 1) * 16);
    const int brb = (l & 7) + ((l >> 4) & 1) * 8;
    const uint32_t bkbx = (uint32_t)(((l >> 3) & 1) * 16);

    float o0 = 0.f, o1 = 0.f;
    const int p0 = tid * 2, p1 = tid * 2 + 1;
    const int r0 = p0 / 7, q0 = p0 % 7;
    const int r1 = p1 / 7, q1 = p1 % 7;
    const bool act = (p0 < 64 * OO);

    float* hsm = (float*)smem;

#pragma unroll 1
    for (int mt = 0; mt < 4; ++mt) {
        const int m0 = mt * 128;
        const __half* wbase = g_wh1h + ((size_t)(n * MMd) + m0 + bmr) * HH;

        uint4 ra[2], rb[4];
        auto fetch = [&](int kc) {
#pragma unroll
            for (int i = 0; i < 2; i++) ra[i] = *(const uint4*)(ybase + kc * 64 + (akw + i) * 8);
#pragma unroll
            for (int i = 0; i < 4; i++) rb[i] = *(const uint4*)(wbase + kc * 64 + (bkw + i) * 8);
        };
        auto store_stage = [&](int s) {
            char* Ab = smem + s * 8192;
            char* Bb = smem + 16384 + s * 16384;
#pragma unroll
            for (int i = 0; i < 2; i++) *(uint4*)(Ab + a_sts[i]) = ra[i];
#pragma unroll
            for (int i = 0; i < 4; i++) *(uint4*)(Bb + b_sts[i]) = rb[i];
        };

        float acc[8][4];
#pragma unroll
        for (int i = 0; i < 8; i++)
#pragma unroll
            for (int j = 0; j < 4; j++) acc[i][j] = 0.f;

        auto compute = [&](int s) {
            uint32_t Ab = sbase + s * 8192;
            uint32_t Bb = sbase + 16384 + s * 16384;
#pragma unroll
            for (int ks = 0; ks < 4; ++ks) {
                uint32_t a[4];
                ldsm4(a, Ab + a_rb + (((uint32_t)(ks * 32) + akbx) ^ a_swz));
                uint32_t bfr[16];
#pragma unroll
                for (int p = 0; p < 4; ++p) {
                    int br = wn * 64 + p * 16 + brb;
                    ldsm4(&bfr[p * 4],
                          Bb + (uint32_t)br * 128 + (((uint32_t)(ks * 32) + bkbx) ^ (uint32_t)((br & 7) << 4)));
                }
#pragma unroll
                for (int nt = 0; nt < 8; ++nt) hmma(acc[nt], a, &bfr[nt * 2]);
            }
        };

        fetch(0);
        store_stage(0);
        fetch(1);
        __syncthreads();
#pragma unroll 1
        for (int kc = 0; kc < 8; ++kc) {
            if (kc < 7) store_stage((kc + 1) & 1);
            if (kc < 6) fetch(kc + 2);
            compute(kc & 1);
            __syncthreads();
        }

        {
            int r = wm * 16 + (l >> 2);
            int cc = (l & 3) * 2;
#pragma unroll
            for (int nt = 0; nt < 8; ++nt) {
                int col = wn * 64 + nt * 8 + cc;
                float bia = bh1[n * MMd + m0 + col];
                float bib = bh1[n * MMd + m0 + col + 1];
                float v0 = acc[nt][0] + bia, v1 = acc[nt][1] + bib;
                float v2 = acc[nt][2] + bia, v3 = acc[nt][3] + bib;
                hsm[r * 132 + col]           = (v0 > 0.f ? v0 : 0.2f * v0);
                hsm[r * 132 + col + 1]       = (v1 > 0.f ? v1 : 0.2f * v1);
                hsm[(r + 8) * 132 + col]     = (v2 > 0.f ? v2 : 0.2f * v2);
                hsm[(r + 8) * 132 + col + 1] = (v3 > 0.f ? v3 : 0.2f * v3);
            }
        }
        __syncthreads();
        if (act) {
            const float* w2a = Wh2 + (size_t)(n * OO + q0) * MMd + m0;
            const float* w2b = Wh2 + (size_t)(n * OO + q1) * MMd + m0;
            float s0 = 0.f, s1 = 0.f;
#pragma unroll 4
            for (int mm = 0; mm < 128; ++mm) {
                s0 += hsm[r0 * 132 + mm] * w2a[mm];
                s1 += hsm[r1 * 132 + mm] * w2b[mm];
            }
            o0 += s0;
            o1 += s1;
        }
        __syncthreads();
    }
    if (act) {
        out[((size_t)(n * BB + b) * TT + (t0 + r0)) * OO + q0] = o0 + bh2[n * OO + q0];
        out[((size_t)(n * BB + b) * TT + (t0 + r1)) * OO + q1] = o1 + bh2[n * OO + q1];
    }
}

// ---------------- launch ----------------
extern "C" void kernel_launch(void* const* d_in, const int* in_sizes, int n_in,
                              void* d_out, int out_size) {
    const float* x     = (const float*)d_in[0];
    const float* Win   = (const float*)d_in[1];
    const float* binp  = (const float*)d_in[2];
    const float* W_ih0 = (const float*)d_in[3];
    const float* W_hh0 = (const float*)d_in[4];
    const float* b_ih0 = (const float*)d_in[5];
    const float* b_hh0 = (const float*)d_in[6];
    const float* W_ih1 = (const float*)d_in[7];
    const float* W_hh1 = (const float*)d_in[8];
    const float* b_ih1 = (const float*)d_in[9];
    const float* b_hh1 = (const float*)d_in[10];
    const float* Wh1   = (const float*)d_in[11];
    const float* bh1   = (const float*)d_in[12];
    const float* Wh2   = (const float*)d_in[13];
    const float* bh2   = (const float*)d_in[14];
    float* out = (float*)d_out;

    cudaFuncSetAttribute(lstm_persist, cudaFuncAttributeMaxDynamicSharedMemorySize, SM_TOTAL_PERSIST);

    // 2 hidden harness launches + these 3 => lstm_persist is profiled launch #6 (-s 5 -c 1)
    init_kernel<<<(NN * BB * HH + 255) / 256, 256>>>();
    input_kernel<<<(BB * TT) / 8, 256>>>(x, Win, binp);
    {
        const long total4 = 4L * (NN * 4 * HH * HH / 4) + (NN * MMd * HH / 4);
        f2h_all<<<(int)((total4 + 255) / 256), 256>>>((const float4*)W_ih0, (const float4*)W_hh0,
                                                      (const float4*)W_ih1, (const float4*)W_hh1,
                                                      (const float4*)Wh1);
    }

    lstm_persist<<<dim3(16, NN, 2), 256, SM_TOTAL_PERSIST>>>(b_ih0, b_hh0, b_ih1, b_hh1);

    head_kernel<<<dim3(256, NN), 256, 49152>>>(bh1, Wh2, bh2, out);
}

// round 17
// speedup vs baseline: 1.0780x; 1.0155x over previous
#include <cuda_runtime.h>
#include <cuda_fp16.h>
#include <math.h>
#include <cstdint>

#define NN 8
#define BB 64
#define TT 256
#define DIN 64
#define HH 512
#define MMd 512
#define OO 7

// ---------------- device globals (no allocation allowed) ----------------
__device__ __half g_z[BB * TT * HH];                 // input-layer output, fp16, [b][t][H]
__device__ __half g_h0[4][NN * BB * HH];             // 4-deep h0 ring
__device__ __half g_h1z[NN * BB * HH];               // zeros (h1 at t=-1); never written
__device__ __half g_y[(size_t)NN * BB * TT * HH];    // layer-1 outputs (= h1 history), fp16
__device__ __half g_wih0[NN * 4 * HH * HH];          // fp16 weight copies
__device__ __half g_whh0[NN * 4 * HH * HH];
__device__ __half g_wih1[NN * 4 * HH * HH];
__device__ __half g_whh1[NN * 4 * HH * HH];
__device__ __half g_wh1h[NN * MMd * HH];             // head Wh1 fp16

// monotonic per-role, per-ensemble barrier counters (16 CTAs per group)
__device__ unsigned g_ctr[2][NN];

// persist smem layout (dynamic):
//   A stage s: @ s*32768, 32KB each = 2 subs x [128 rows][128B] swizzled
//   B stage s: @ 65536 + s*16384, 16KB each = 2 subs x [64 rows][128B]
//   total 98304.
#define SMA(s)   ((s) * 32768)
#define SMB(s)   (65536 + (s) * 16384)
#define SM_TOTAL_PERSIST 98304

// ---------------- helpers ----------------
__device__ __forceinline__ uint32_t smem_u32(const void* p) {
    uint32_t a;
    asm("{ .reg .u64 t; cvta.to.shared.u64 t, %1; cvt.u32.u64 %0, t; }" : "=r"(a) : "l"(p));
    return a;
}
__device__ __forceinline__ void ldsm4(uint32_t* r, uint32_t addr) {
    asm volatile("ldmatrix.sync.aligned.m8n8.x4.shared.b16 {%0,%1,%2,%3}, [%4];"
                 : "=r"(r[0]), "=r"(r[1]), "=r"(r[2]), "=r"(r[3]) : "r"(addr));
}
__device__ __forceinline__ void hmma(float* d, const uint32_t* a, const uint32_t* b) {
    asm volatile(
        "mma.sync.aligned.m16n8k16.row.col.f32.f16.f16.f32 "
        "{%0,%1,%2,%3}, {%4,%5,%6,%7}, {%8,%9}, {%0,%1,%2,%3};"
        : "+f"(d[0]), "+f"(d[1]), "+f"(d[2]), "+f"(d[3])
        : "r"(a[0]), "r"(a[1]), "r"(a[2]), "r"(a[3]), "r"(b[0]), "r"(b[1]));
}
__device__ __forceinline__ void cp16(uint32_t dst, const void* src) {
    asm volatile("cp.async.cg.shared.global [%0], [%1], 16;" :: "r"(dst), "l"(src) : "memory");
}
__device__ __forceinline__ void cp_commit() {
    asm volatile("cp.async.commit_group;" ::: "memory");
}
__device__ __forceinline__ void cp_wait1() {
    asm volatile("cp.async.wait_group 1;" ::: "memory");
}
__device__ __forceinline__ void cp_wait0() {
    asm volatile("cp.async.wait_group 0;" ::: "memory");
}
__device__ __forceinline__ float ex2f(float x) {
    float r; asm("ex2.approx.f32 %0, %1;" : "=f"(r) : "f"(x)); return r;
}
__device__ __forceinline__ float rcpf(float x) {
    float r; asm("rcp.approx.f32 %0, %1;" : "=f"(r) : "f"(x)); return r;
}
__device__ __forceinline__ float sigf(float x) {          // 1/(1+e^-x), ~1e-6 rel err
    return rcpf(1.0f + ex2f(-1.4426950408889634f * x));
}
__device__ __forceinline__ float tanhf_fast(float x) {    // 2*sig(2x)-1
    return fmaf(2.0f, rcpf(1.0f + ex2f(-2.8853900817779268f * x)), -1.0f);
}

// ---------------- init ----------------
__global__ void init_kernel() {
    int i = blockIdx.x * blockDim.x + threadIdx.x;
    if (i < NN * BB * HH) {
        g_h0[0][i] = __float2half(0.f);   // h0_{-1}; other slots written before read
    }
    if (blockIdx.x == 0 && threadIdx.x < 2 * NN) {
        g_ctr[threadIdx.x >> 3][threadIdx.x & 7] = 0u;
    }
}

// ---------------- all weight fp32 -> fp16 in one launch ----------------
__global__ void __launch_bounds__(256) f2h_all(const float4* __restrict__ w0,
                                               const float4* __restrict__ w1,
                                               const float4* __restrict__ w2,
                                               const float4* __restrict__ w3,
                                               const float4* __restrict__ wh) {
    const long NW = (long)NN * 4 * HH * HH / 4;
    const long NH = (long)NN * MMd * HH / 4;
    long i = (long)blockIdx.x * 256 + threadIdx.x;
    const float4* src; __half2* dst; long o;
    if (i < NW)            { src = w0; dst = (__half2*)g_wih0; o = i; }
    else if (i < 2 * NW)   { src = w1; dst = (__half2*)g_whh0; o = i - NW; }
    else if (i < 3 * NW)   { src = w2; dst = (__half2*)g_wih1; o = i - 2 * NW; }
    else if (i < 4 * NW)   { src = w3; dst = (__half2*)g_whh1; o = i - 3 * NW; }
    else if (i < 4 * NW + NH) { src = wh; dst = (__half2*)g_wh1h; o = i - 4 * NW; }
    else return;
    float4 v = src[o];
    dst[2 * o]     = __floats2half2_rn(v.x, v.y);
    dst[2 * o + 1] = __floats2half2_rn(v.z, v.w);
}

// ---------------- input layer ----------------
__global__ void __launch_bounds__(256) input_kernel(const float* __restrict__ x,
                                                    const float* __restrict__ Win,
                                                    const float* __restrict__ binp) {
    int tok0 = blockIdx.x * 8;
    int tid = threadIdx.x;
    __shared__ float xs[8][DIN];
    for (int i = tid; i < 8 * DIN; i += 256) xs[i >> 6][i & 63] = x[(size_t)tok0 * DIN + i];
    __syncthreads();
    int c0 = tid, c1 = tid + 256;
    float a0[8], a1[8];
#pragma unroll
    for (int k = 0; k < 8; k++) { a0[k] = 0.f; a1[k] = 0.f; }
    const float* w0 = Win + (size_t)c0 * DIN;
    const float* w1 = Win + (size_t)c1 * DIN;
    for (int k = 0; k < DIN; k++) {
        float wv0 = w0[k], wv1 = w1[k];
#pragma unroll
        for (int tk = 0; tk < 8; tk++) {
            a0[tk] += wv0 * xs[tk][k];
            a1[tk] += wv1 * xs[tk][k];
        }
    }
    float bb0 = binp[c0], bb1 = binp[c1];
#pragma unroll
    for (int tk = 0; tk < 8; tk++) {
        float v0 = a0[tk] + bb0;
        v0 = (v0 > 0.f ? v0 : 0.2f * v0) * 10.0f;
        g_z[(size_t)(tok0 + tk) * HH + c0] = __float2half(v0);
        float v1 = a1[tk] + bb1;
        v1 = (v1 > 0.f ? v1 : 0.2f * v1) * 10.0f;
        g_z[(size_t)(tok0 + tk) * HH + c1] = __float2half(v1);
    }
}

// ---------------- persistent wavefront kernel ----------------
// Grid (16, 8, 2): role 0 = layer-0 CTA, role 1 = layer-1 CTA. 256 CTAs, 2/SM.
// Role 0 at step s computes l0[t=s] (s<TT).
// Role 1 LAGS 2: at step s computes l1[t=s-2] (s>=2); its B chunks 0,1 (A + h0_t)
// are prefetched pre-barrier (h0_t certified one barrier early), no in-phase reissue.
// A rows gate-interleaved -> register-only cell epilogue.
__global__ void __launch_bounds__(256, 2) lstm_persist(const float* __restrict__ b_ih0,
                                                       const float* __restrict__ b_hh0,
                                                       const float* __restrict__ b_ih1,
                                                       const float* __restrict__ b_hh1) {
    extern __shared__ char smem[];
    const int jt = blockIdx.x, n = blockIdx.y, role = blockIdx.z;
    const int tid = threadIdx.x;
    const int wid = tid >> 5, l = tid & 31;
    uint32_t sbase = smem_u32(smem);

    // coalesced loader constants: lane u = tid>>3 picks row-in-band, (tid&7)*16B within row
    const int u = tid >> 3;
    const int lane8 = (tid & 7) * 8;       // halves
    // gate-interleaved A source: band i, band-row u -> gate u>>3, j = jt*32 + i*8 + (u&7)
    int growOff[4];
    uint32_t stsA[4];
#pragma unroll
    for (int i = 0; i < 4; ++i) {
        const int row = i * 32 + u;
        growOff[i] = (((u >> 3) * HH) + jt * 32 + i * 8 + (u & 7)) * HH + lane8;
        stsA[i] = (uint32_t)(row * 128 + (((tid & 7) * 16) ^ ((row & 7) << 4)));
    }
    uint32_t stsB[2];
#pragma unroll
    for (int i = 0; i < 2; ++i) {
        const int row = i * 32 + u;
        stsB[i] = (uint32_t)(row * 128 + (((tid & 7) * 16) ^ ((row & 7) << 4)));
    }
    const int b0 = u, b1 = 32 + u;
    const int hOff0 = (n * BB + b0) * HH + lane8;
    const int hOff1 = (n * BB + b1) * HH + lane8;

    // A weight streams per role (lo = chunks 0-3, hi = chunks 4-7)
    const __half* A_lo = (role ? g_wih1 : g_wih0) + (size_t)n * 4 * HH * HH;
    const __half* A_hi = (role ? g_whh1 : g_whh0) + (size_t)n * 4 * HH * HH;

    // fragment mappings (32x32 warp tiles: wm = wid&3 rows, wn = wid>>2 cols)
    const int wm = wid & 3, wn = wid >> 2;
    const int wnB = wn * 32;
    const int arow0 = wm * 32 + (l & 15);
    const int aunit = (l >> 4) & 1;
    const int brow0 = wnB + (l & 7) + ((l >> 4) & 1) * 8;
    const int bunit = (l >> 3) & 1;

    // epilogue coordinates: jcol fixed, 8 b-values
    const int jcol = jt * 32 + wm * 8 + (l >> 2);
    float bias_g[4];
    {
        const float* ba = role ? b_ih1 : b_ih0;
        const float* bb = role ? b_hh1 : b_hh0;
#pragma unroll
        for (int g = 0; g < 4; ++g) {
            const int wr = n * 4 * HH + g * HH + jcol;
            bias_g[g] = ba[wr] + bb[wr];
        }
    }

    float c_reg[8];
#pragma unroll
    for (int k = 0; k < 8; ++k) c_reg[k] = 0.f;

    auto issueA = [&](int c) {   // A half-chunk: 32KB across CTA
        const __half* srcA = (c < 4) ? A_lo : A_hi;
        const int kh = (c & 3) * 128;
        const uint32_t sA = sbase + SMA(c & 1);
#pragma unroll
        for (int p = 0; p < 8; ++p) {
            const int q = p >> 2, i = p & 3;
            cp16(sA + q * 16384 + stsA[i], srcA + growOff[i] + kh + q * 64);
        }
    };
    auto issueB = [&](int c, const __half* r0, const __half* r1) {   // B: 16KB across CTA
        const int kh = (c & 3) * 128;
        const uint32_t sB = sbase + SMB(c & 1);
#pragma unroll
        for (int p = 0; p < 4; ++p) {
            const int q = p >> 1, i = p & 1;
            cp16(sB + q * 8192 + stsB[i], (i ? r1 : r0) + kh + q * 64);
        }
    };

    // initial prefetch: role0 -> chunks 0,1 of phase t=0 (A + z). role1: nothing
    // (its first active phase is s=2; prefetch happens at end of s=1).
    if (role == 0) {
        const __half* z0 = g_z + ((size_t)b0 * TT + 0) * HH + lane8;
        const __half* z1 = g_z + ((size_t)b1 * TT + 0) * HH + lane8;
        issueA(0); issueB(0, z0, z1); cp_commit();
        issueA(1); issueB(1, z0, z1); cp_commit();
    }

#pragma unroll 1
    for (int s = 0; s <= TT + 1; ++s) {
        const bool active = role == 0 ? (s < TT) : (s >= 2);
        if (active) {
            const int t = role == 0 ? s : s - 2;
            const __half *L0, *L1, *H0, *H1;
            __half* Hout = 0;
            if (role == 0) {
                L0 = g_z + ((size_t)b0 * TT + t) * HH + lane8;
                L1 = g_z + ((size_t)b1 * TT + t) * HH + lane8;
                H0 = g_h0[t & 3] + hOff0;  H1 = g_h0[t & 3] + hOff1;   // h0_{t-1}
                Hout = g_h0[(t + 1) & 3];
            } else {
                // chunks 0,1 (A_lo + h0_t) already in flight from pre-barrier prefetch
                L0 = g_h0[(t + 1) & 3] + hOff0;  L1 = g_h0[(t + 1) & 3] + hOff1;   // h0_t
                if (t == 0) {
                    H0 = g_h1z + hOff0;  H1 = g_h1z + hOff1;
                } else {
                    H0 = g_y + ((size_t)((n * BB + b0) * TT) + (t - 1)) * HH + lane8;
                    H1 = g_y + ((size_t)((n * BB + b1) * TT) + (t - 1)) * HH + lane8;
                }
            }

            float acc[2][4][4];
#pragma unroll
            for (int i = 0; i < 2; i++)
#pragma unroll
                for (int j = 0; j < 4; j++)
#pragma unroll
                    for (int k = 0; k < 4; k++) acc[i][j][k] = 0.f;

            auto compute = [&](int st) {
                const uint32_t Ab = sbase + SMA(st);
                const uint32_t Bb = sbase + SMB(st);
#pragma unroll
                for (int ks = 0; ks < 8; ++ks) {
                    const int q = ks >> 2, ksl = ks & 3;
                    uint32_t afr[2][4], bfr[2][4];
#pragma unroll
                    for (int mi = 0; mi < 2; ++mi) {
                        const int row = arow0 + mi * 16;
                        const uint32_t off = ((uint32_t)((ksl * 2 + aunit) * 16)) ^ ((uint32_t)((row & 7) << 4));
                        ldsm4(afr[mi], Ab + (uint32_t)(q * 16384 + row * 128) + off);
                    }
#pragma unroll
                    for (int cb = 0; cb < 2; ++cb) {
                        const int col = brow0 + cb * 16;
                        const uint32_t off = ((uint32_t)((ksl * 2 + bunit) * 16)) ^ ((uint32_t)((col & 7) << 4));
                        ldsm4(bfr[cb], Bb + (uint32_t)(q * 8192 + col * 128) + off);
                    }
#pragma unroll
                    for (int mi = 0; mi < 2; ++mi)
#pragma unroll
                        for (int nt = 0; nt < 4; ++nt)
                            hmma(acc[mi][nt], afr[mi], &bfr[nt >> 1][(nt & 1) * 2]);
                }
            };

#pragma unroll 1
            for (int c = 0; c < 8; ++c) {
                if (c < 7) cp_wait1(); else cp_wait0();
                __syncthreads();
                compute(c & 1);
                __syncthreads();
                if (c + 2 < 8) {
                    const int cn = c + 2;
                    issueA(cn);
                    if (cn < 4) issueB(cn, L0, L1);
                    else        issueB(cn, H0, H1);
                    cp_commit();
                }
            }

            // role0 next-phase prefetch (z is barrier-independent)
            if (role == 0 && s + 1 < TT) {
                const __half* z0 = g_z + ((size_t)b0 * TT + (s + 1)) * HH + lane8;
                const __half* z1 = g_z + ((size_t)b1 * TT + (s + 1)) * HH + lane8;
                issueA(0); issueB(0, z0, z1); cp_commit();
                issueA(1); issueB(1, z0, z1); cp_commit();
            }

            // register-only epilogue: acc[0][nt][e]=i, acc[0][nt][2+e]=f,
            // acc[1][nt][e]=g, acc[1][nt][2+e]=o, for b = wnB + nt*8 + 2*(l&3) + e
#pragma unroll
            for (int nt = 0; nt < 4; ++nt) {
#pragma unroll
                for (int e = 0; e < 2; ++e) {
                    const int k = nt * 2 + e;
                    const int b = wnB + nt * 8 + 2 * (l & 3) + e;
                    float gi = acc[0][nt][e]     + bias_g[0];
                    float gf = acc[0][nt][2 + e] + bias_g[1];
                    float gg = acc[1][nt][e]     + bias_g[2];
                    float go = acc[1][nt][2 + e] + bias_g[3];
                    float cn = sigf(gf) * c_reg[k] + sigf(gi) * tanhf_fast(gg);
                    float hn = sigf(go) * tanhf_fast(cn);
                    c_reg[k] = cn;
                    if (role == 0)
                        Hout[(n * BB + b) * HH + jcol] = __float2half(hn);
                    else
                        g_y[((size_t)(n * BB + b) * TT + t) * HH + jcol] = __float2half(hn);
                }
            }
        }

        // role1 pre-barrier prefetch for step s+1 (t' = s-1): chunks 0,1 = A_lo + h0_{s-1},
        // certified by ctr0 >= 16*s (held since entering step s).
        if (role == 1 && s >= 1 && s <= TT) {
            const __half* p0 = g_h0[s & 3] + hOff0;   // h0_{s-1} lives at slot s&3
            const __half* p1 = g_h0[s & 3] + hOff1;
            issueA(0); issueB(0, p0, p1); cp_commit();
            issueA(1); issueB(1, p0, p1); cp_commit();
        }

        // ---- barrier (monotonic counters) ----
        if (s <= TT) {
            __threadfence();   // publish h0/y stores before arrive
            if (tid == 0) {
                atomicAdd(&g_ctr[role][n], 1u);
                const unsigned ns = (unsigned)(s + 1);
                volatile unsigned* c0 = &g_ctr[0][n];
                volatile unsigned* c1 = &g_ctr[1][n];
                if (role == 0) {
                    if (ns < TT) {
                        const unsigned t0v = 16u * ns, t1v = 16u * (ns - 1);
                        while (*c0 < t0v || *c1 < t1v) { }   // h0 ring depth 4, role1 lag 2
                    }
                } else {
                    const unsigned tv = 16u * ns;
                    while (*c1 < tv || *c0 < tv) { }         // makes h0 prefetch safe next step
                }
            }
            __syncthreads();
        }
    }
}

// ---------------- fused head (unchanged, known-good) ----------------
__global__ void __launch_bounds__(256) head_kernel(const float* __restrict__ bh1,
                                                   const float* __restrict__ Wh2,
                                                   const float* __restrict__ bh2,
                                                   float* __restrict__ out) {
    extern __shared__ char smem[];
    const int n = blockIdx.y;
    const int rt = blockIdx.x;
    const int b = rt >> 2;
    const int t0 = (rt & 3) * 64;
    const int tid = threadIdx.x;
    const int wid = tid >> 5, l = tid & 31;
    const int wm = wid & 3, wn = wid >> 2;
    uint32_t sbase = smem_u32(smem);

    const int am = tid >> 2, akw = (tid & 3) * 2;
    const __half* ybase = g_y + ((size_t)((n * BB + b) * TT) + t0 + am) * HH;
    uint32_t a_sts[2];
#pragma unroll
    for (int i = 0; i < 2; i++) a_sts[i] = (uint32_t)((am * 128 + (akw + i) * 16) ^ ((((am * 128 + (akw + i) * 16) >> 3) & 0x70)));
    const int bmr = tid >> 1, bkw = (tid & 1) * 4;
    uint32_t b_sts[4];
#pragma unroll
    for (int i = 0; i < 4; i++) b_sts[i] = (uint32_t)((bmr * 128 + (bkw + i) * 16) ^ ((((bmr * 128 + (bkw + i) * 16) >> 3) & 0x70)));

    const int arow = wm * 16 + (l & 7) + ((l >> 3) & 1) * 8;
    const uint32_t a_rb = (uint32_t)arow * 128u;
    const uint32_t a_swz = (uint32_t)((arow & 7) << 4);
    const uint32_t akbx = (uint32_t)(((l >> 4) & 1) * 16);
    const int brb = (l & 7) + ((l >> 4) & 1) * 8;
    const uint32_t bkbx = (uint32_t)(((l >> 3) & 1) * 16);

    float o0 = 0.f, o1 = 0.f;
    const int p0 = tid * 2, p1 = tid * 2 + 1;
    const int r0 = p0 / 7, q0 = p0 % 7;
    const int r1 = p1 / 7, q1 = p1 % 7;
    const bool act = (p0 < 64 * OO);

    float* hsm = (float*)smem;

#pragma unroll 1
    for (int mt = 0; mt < 4; ++mt) {
        const int m0 = mt * 128;
        const __half* wbase = g_wh1h + ((size_t)(n * MMd) + m0 + bmr) * HH;

        uint4 ra[2], rb[4];
        auto fetch = [&](int kc) {
#pragma unroll
            for (int i = 0; i < 2; i++) ra[i] = *(const uint4*)(ybase + kc * 64 + (akw + i) * 8);
#pragma unroll
            for (int i = 0; i < 4; i++) rb[i] = *(const uint4*)(wbase + kc * 64 + (bkw + i) * 8);
        };
        auto store_stage = [&](int s) {
            char* Ab = smem + s * 8192;
            char* Bb = smem + 16384 + s * 16384;
#pragma unroll
            for (int i = 0; i < 2; i++) *(uint4*)(Ab + a_sts[i]) = ra[i];
#pragma unroll
            for (int i = 0; i < 4; i++) *(uint4*)(Bb + b_sts[i]) = rb[i];
        };

        float acc[8][4];
#pragma unroll
        for (int i = 0; i < 8; i++)
#pragma unroll
            for (int j = 0; j < 4; j++) acc[i][j] = 0.f;

        auto compute = [&](int s) {
            uint32_t Ab = sbase + s * 8192;
            uint32_t Bb = sbase + 16384 + s * 16384;
#pragma unroll
            for (int ks = 0; ks < 4; ++ks) {
                uint32_t a[4];
                ldsm4(a, Ab + a_rb + (((uint32_t)(ks * 32) + akbx) ^ a_swz));
                uint32_t bfr[16];
#pragma unroll
                for (int p = 0; p < 4; ++p) {
                    int br = wn * 64 + p * 16 + brb;
                    ldsm4(&bfr[p * 4],
                          Bb + (uint32_t)br * 128 + (((uint32_t)(ks * 32) + bkbx) ^ (uint32_t)((br & 7) << 4)));
                }
#pragma unroll
                for (int nt = 0; nt < 8; ++nt) hmma(acc[nt], a, &bfr[nt * 2]);
            }
        };

        fetch(0);
        store_stage(0);
        fetch(1);
        __syncthreads();
#pragma unroll 1
        for (int kc = 0; kc < 8; ++kc) {
            if (kc < 7) store_stage((kc + 1) & 1);
            if (kc < 6) fetch(kc + 2);
            compute(kc & 1);
            __syncthreads();
        }

        {
            int r = wm * 16 + (l >> 2);
            int cc = (l & 3) * 2;
#pragma unroll
            for (int nt = 0; nt < 8; ++nt) {
                int col = wn * 64 + nt * 8 + cc;
                float bia = bh1[n * MMd + m0 + col];
                float bib = bh1[n * MMd + m0 + col + 1];
                float v0 = acc[nt][0] + bia, v1 = acc[nt][1] + bib;
                float v2 = acc[nt][2] + bia, v3 = acc[nt][3] + bib;
                hsm[r * 132 + col]           = (v0 > 0.f ? v0 : 0.2f * v0);
                hsm[r * 132 + col + 1]       = (v1 > 0.f ? v1 : 0.2f * v1);
                hsm[(r + 8) * 132 + col]     = (v2 > 0.f ? v2 : 0.2f * v2);
                hsm[(r + 8) * 132 + col + 1] = (v3 > 0.f ? v3 : 0.2f * v3);
            }
        }
        __syncthreads();
        if (act) {
            const float* w2a = Wh2 + (size_t)(n * OO + q0) * MMd + m0;
            const float* w2b = Wh2 + (size_t)(n * OO + q1) * MMd + m0;
            float s0 = 0.f, s1 = 0.f;
#pragma unroll 4
            for (int mm = 0; mm < 128; ++mm) {
                s0 += hsm[r0 * 132 + mm] * w2a[mm];
                s1 += hsm[r1 * 132 + mm] * w2b[mm];
            }
            o0 += s0;
            o1 += s1;
        }
        __syncthreads();
    }
    if (act) {
        out[((size_t)(n * BB + b) * TT + (t0 + r0)) * OO + q0] = o0 + bh2[n * OO + q0];
        out[((size_t)(n * BB + b) * TT + (t0 + r1)) * OO + q1] = o1 + bh2[n * OO + q1];
    }
}

// ---------------- launch ----------------
extern "C" void kernel_launch(void* const* d_in, const int* in_sizes, int n_in,
                              void* d_out, int out_size) {
    const float* x     = (const float*)d_in[0];
    const float* Win   = (const float*)d_in[1];
    const float* binp  = (const float*)d_in[2];
    const float* W_ih0 = (const float*)d_in[3];
    const float* W_hh0 = (const float*)d_in[4];
    const float* b_ih0 = (const float*)d_in[5];
    const float* b_hh0 = (const float*)d_in[6];
    const float* W_ih1 = (const float*)d_in[7];
    const float* W_hh1 = (const float*)d_in[8];
    const float* b_ih1 = (const float*)d_in[9];
    const float* b_hh1 = (const float*)d_in[10];
    const float* Wh1   = (const float*)d_in[11];
    const float* bh1   = (const float*)d_in[12];
    const float* Wh2   = (const float*)d_in[13];
    const float* bh2   = (const float*)d_in[14];
    float* out = (float*)d_out;

    cudaFuncSetAttribute(lstm_persist, cudaFuncAttributeMaxDynamicSharedMemorySize, SM_TOTAL_PERSIST);

    // 2 hidden harness launches + these 3 => lstm_persist is profiled launch #6 (-s 5 -c 1)
    init_kernel<<<(NN * BB * HH + 255) / 256, 256>>>();
    input_kernel<<<(BB * TT) / 8, 256>>>(x, Win, binp);
    {
        const long total4 = 4L * (NN * 4 * HH * HH / 4) + (NN * MMd * HH / 4);
        f2h_all<<<(int)((total4 + 255) / 256), 256>>>((const float4*)W_ih0, (const float4*)W_hh0,
                                                      (const float4*)W_ih1, (const float4*)W_hh1,
                                                      (const float4*)Wh1);
    }

    lstm_persist<<<dim3(16, NN, 2), 256, SM_TOTAL_PERSIST>>>(b_ih0, b_hh0, b_ih1, b_hh1);

    head_kernel<<<dim3(256, NN), 256, 49152>>>(bh1, Wh2, bh2, out);
}